// round 1
// baseline (speedup 1.0000x reference)
#include <cuda_runtime.h>

#define LNEPS 1e-3f
#define SCALAR 0.0625f   // 1/sqrt(256)

// ---------------- scratch (device globals; no allocations allowed) ----------
__device__ float g_Fn[2048 * 256];        // LayerNorm(F)
__device__ float g_Q[2048 * 256];
__device__ float g_K[2048 * 256];
__device__ float g_L[4 * 512 * 512];      // scaled logits: scalar*(QK^T + bias)
__device__ float g_vsum[2048];            // row sums of V
__device__ float g_sd[64];                // scalar * g_p[d] * w_eff[d]
__device__ float g_sc[2];                 // [0]=sum(g_sd), [1]=scalar*const term
__device__ float g_wvsum[256];            // Wv @ ones

// ---------------- kernel 1: fold weights ------------------------------------
__global__ __launch_bounds__(256) void prep_kernel(
    const float* __restrict__ Wv, const float* __restrict__ gp,
    const float* __restrict__ bp, const float* __restrict__ Wpt,
    const float* __restrict__ bpt, const float* __restrict__ Wph)
{
    __shared__ float weff[64];
    int t = threadIdx.x;
    if (t < 64) {
        float acc = 0.f;
        for (int p = 0; p < 128; ++p) acc += Wpt[t * 128 + p] * Wph[p];
        weff[t] = acc;
        g_sd[t] = SCALAR * gp[t] * acc;
    }
    // wv_sum[f] = sum_a Wv[f,a]
    {
        float acc = 0.f;
        const float* row = Wv + t * 256;
        for (int a = 0; a < 256; ++a) acc += row[a];
        g_wvsum[t] = acc;
    }
    __syncthreads();
    if (t == 0) {
        float S = 0.f, C = 0.f;
        for (int d = 0; d < 64; ++d) { S += g_sd[d]; C += bp[d] * weff[d]; }
        float C2 = 0.f;
        for (int p = 0; p < 128; ++p) C2 += bpt[p] * Wph[p];
        g_sc[0] = S;
        g_sc[1] = SCALAR * (C + C2);
    }
}

// ---------------- kernel 2: LayerNorm(F) + vsum ------------------------------
// 1 warp per row of 256 floats; 8 rows per block.
__global__ __launch_bounds__(256) void ln_kernel(
    const float* __restrict__ F, const float* __restrict__ gf,
    const float* __restrict__ bf)
{
    int row  = blockIdx.x * 8 + (threadIdx.x >> 5);
    int lane = threadIdx.x & 31;
    const float* x = F + (size_t)row * 256;
    float4 a = *(const float4*)(x + lane * 4);
    float4 b = *(const float4*)(x + 128 + lane * 4);
    float s = a.x + a.y + a.z + a.w + b.x + b.y + b.z + b.w;
    float q = a.x*a.x + a.y*a.y + a.z*a.z + a.w*a.w
            + b.x*b.x + b.y*b.y + b.z*b.z + b.w*b.w;
    #pragma unroll
    for (int o = 16; o; o >>= 1) {
        s += __shfl_xor_sync(0xffffffffu, s, o);
        q += __shfl_xor_sync(0xffffffffu, q, o);
    }
    float mu   = s * (1.f / 256.f);
    float rinv = rsqrtf(q * (1.f / 256.f) - mu * mu + LNEPS);

    float4 g0 = *(const float4*)(gf + lane * 4);
    float4 b0 = *(const float4*)(bf + lane * 4);
    float4 g1 = *(const float4*)(gf + 128 + lane * 4);
    float4 b1 = *(const float4*)(bf + 128 + lane * 4);
    float4 f0, f1;
    f0.x = (a.x - mu) * rinv * g0.x + b0.x;
    f0.y = (a.y - mu) * rinv * g0.y + b0.y;
    f0.z = (a.z - mu) * rinv * g0.z + b0.z;
    f0.w = (a.w - mu) * rinv * g0.w + b0.w;
    f1.x = (b.x - mu) * rinv * g1.x + b1.x;
    f1.y = (b.y - mu) * rinv * g1.y + b1.y;
    f1.z = (b.z - mu) * rinv * g1.z + b1.z;
    f1.w = (b.w - mu) * rinv * g1.w + b1.w;

    *(float4*)(g_Fn + (size_t)row * 256 + lane * 4)       = f0;
    *(float4*)(g_Fn + (size_t)row * 256 + 128 + lane * 4) = f1;

    float4 w0 = *(const float4*)(g_wvsum + lane * 4);
    float4 w1 = *(const float4*)(g_wvsum + 128 + lane * 4);
    float p = f0.x*w0.x + f0.y*w0.y + f0.z*w0.z + f0.w*w0.w
            + f1.x*w1.x + f1.y*w1.y + f1.z*w1.z + f1.w*w1.w;
    #pragma unroll
    for (int o = 16; o; o >>= 1) p += __shfl_xor_sync(0xffffffffu, p, o);
    if (lane == 0) g_vsum[row] = p;
}

// ---------------- kernel 3: Q = Fn@Wq, K = Fn@Wk  (NN GEMM, 64x64 tile) ------
__global__ __launch_bounds__(256) void gemm_qk(
    const float* __restrict__ Wq, const float* __restrict__ Wk)
{
    const float* W = blockIdx.z ? Wk : Wq;
    float* C = blockIdx.z ? g_K : g_Q;
    __shared__ float As[16][68];   // [k][m], padded stride 68 (16B-aligned)
    __shared__ float Ws[16][68];   // [k][n]
    int t  = threadIdx.x;
    int tx = t & 15, ty = t >> 4;
    int m0 = blockIdx.y * 64, n0 = blockIdx.x * 64;
    float acc[4][4] = {};
    for (int k0 = 0; k0 < 256; k0 += 16) {
        float4 av = *(const float4*)(g_Fn + (size_t)(m0 + (t >> 2)) * 256 + k0 + (t & 3) * 4);
        int km = (t & 3) * 4, mm = t >> 2;
        As[km + 0][mm] = av.x; As[km + 1][mm] = av.y;
        As[km + 2][mm] = av.z; As[km + 3][mm] = av.w;
        float4 wv = *(const float4*)(W + (size_t)(k0 + (t >> 4)) * 256 + n0 + (t & 15) * 4);
        *(float4*)&Ws[t >> 4][(t & 15) * 4] = wv;
        __syncthreads();
        #pragma unroll
        for (int k = 0; k < 16; ++k) {
            float4 a = *(float4*)&As[k][ty * 4];
            float4 w = *(float4*)&Ws[k][tx * 4];
            acc[0][0] += a.x * w.x; acc[0][1] += a.x * w.y; acc[0][2] += a.x * w.z; acc[0][3] += a.x * w.w;
            acc[1][0] += a.y * w.x; acc[1][1] += a.y * w.y; acc[1][2] += a.y * w.z; acc[1][3] += a.y * w.w;
            acc[2][0] += a.z * w.x; acc[2][1] += a.z * w.y; acc[2][2] += a.z * w.z; acc[2][3] += a.z * w.w;
            acc[3][0] += a.w * w.x; acc[3][1] += a.w * w.y; acc[3][2] += a.w * w.z; acc[3][3] += a.w * w.w;
        }
        __syncthreads();
    }
    #pragma unroll
    for (int i = 0; i < 4; ++i) {
        float4 o;
        o.x = acc[i][0]; o.y = acc[i][1]; o.z = acc[i][2]; o.w = acc[i][3];
        *(float4*)(C + (size_t)(m0 + ty * 4 + i) * 256 + n0 + tx * 4) = o;
    }
}

// ---------------- kernel 4: pair bias from D (HBM-bound) ---------------------
// bias'[row] = rinv * (dot(D_row, s') - mu*S') + C'   (pre-scaled by SCALAR)
// 16 lanes per 64-float row (float4 each); 16 rows per 256-thread block.
__global__ __launch_bounds__(256) void bias_kernel(const float* __restrict__ D)
{
    size_t row = (size_t)blockIdx.x * 16 + (threadIdx.x >> 4);
    int c = threadIdx.x & 15;
    float4 v = *(const float4*)(D + row * 64 + c * 4);
    float4 s = *(const float4*)(g_sd + c * 4);
    float sum = v.x + v.y + v.z + v.w;
    float sq  = v.x*v.x + v.y*v.y + v.z*v.z + v.w*v.w;
    float dp  = v.x*s.x + v.y*s.y + v.z*s.z + v.w*s.w;
    #pragma unroll
    for (int o = 8; o; o >>= 1) {
        sum += __shfl_xor_sync(0xffffffffu, sum, o);
        sq  += __shfl_xor_sync(0xffffffffu, sq, o);
        dp  += __shfl_xor_sync(0xffffffffu, dp, o);
    }
    if (c == 0) {
        float mu   = sum * (1.f / 64.f);
        float rinv = rsqrtf(sq * (1.f / 64.f) - mu * mu + LNEPS);
        g_L[row] = rinv * (dp - mu * g_sc[0]) + g_sc[1];
    }
}

// ---------------- kernel 5: L += SCALAR * Q @ K^T per batch (NT GEMM) --------
__global__ __launch_bounds__(256) void gemm_att()
{
    int b = blockIdx.z;
    const float* Q = g_Q + (size_t)b * 512 * 256;
    const float* K = g_K + (size_t)b * 512 * 256;
    float* C = g_L + (size_t)b * 512 * 512;
    __shared__ float As[16][68];
    __shared__ float Bs[16][68];
    int t  = threadIdx.x;
    int tx = t & 15, ty = t >> 4;
    int m0 = blockIdx.y * 64, n0 = blockIdx.x * 64;
    float acc[4][4] = {};
    for (int k0 = 0; k0 < 256; k0 += 16) {
        int km = (t & 3) * 4, mm = t >> 2;
        float4 av = *(const float4*)(Q + (size_t)(m0 + mm) * 256 + k0 + km);
        As[km + 0][mm] = av.x; As[km + 1][mm] = av.y;
        As[km + 2][mm] = av.z; As[km + 3][mm] = av.w;
        float4 bv = *(const float4*)(K + (size_t)(n0 + mm) * 256 + k0 + km);
        Bs[km + 0][mm] = bv.x; Bs[km + 1][mm] = bv.y;
        Bs[km + 2][mm] = bv.z; Bs[km + 3][mm] = bv.w;
        __syncthreads();
        #pragma unroll
        for (int k = 0; k < 16; ++k) {
            float4 a = *(float4*)&As[k][ty * 4];
            float4 w = *(float4*)&Bs[k][tx * 4];
            acc[0][0] += a.x * w.x; acc[0][1] += a.x * w.y; acc[0][2] += a.x * w.z; acc[0][3] += a.x * w.w;
            acc[1][0] += a.y * w.x; acc[1][1] += a.y * w.y; acc[1][2] += a.y * w.z; acc[1][3] += a.y * w.w;
            acc[2][0] += a.z * w.x; acc[2][1] += a.z * w.y; acc[2][2] += a.z * w.z; acc[2][3] += a.z * w.w;
            acc[3][0] += a.w * w.x; acc[3][1] += a.w * w.y; acc[3][2] += a.w * w.z; acc[3][3] += a.w * w.w;
        }
        __syncthreads();
    }
    #pragma unroll
    for (int i = 0; i < 4; ++i) {
        float* cp = C + (size_t)(m0 + ty * 4 + i) * 512 + n0 + tx * 4;
        float4 old = *(float4*)cp;
        old.x += SCALAR * acc[i][0];
        old.y += SCALAR * acc[i][1];
        old.z += SCALAR * acc[i][2];
        old.w += SCALAR * acc[i][3];
        *(float4*)cp = old;
    }
}

// ---------------- kernel 6: softmax + weighted vsum reduction ----------------
__global__ __launch_bounds__(256) void softmax_kernel(float* __restrict__ out)
{
    int row = blockIdx.x;                     // row = b*512 + q
    const float* l  = g_L + (size_t)row * 512;
    const float* vb = g_vsum + ((row >> 9) << 9);
    int t = threadIdx.x;
    int lane = t & 31, wid = t >> 5;
    float l0 = l[t], l1 = l[t + 256];
    float v0 = vb[t], v1 = vb[t + 256];
    float m = fmaxf(l0, l1);
    #pragma unroll
    for (int o = 16; o; o >>= 1) m = fmaxf(m, __shfl_xor_sync(0xffffffffu, m, o));
    __shared__ float smax[8];
    if (lane == 0) smax[wid] = m;
    __syncthreads();
    float bm = smax[0];
    #pragma unroll
    for (int w = 1; w < 8; ++w) bm = fmaxf(bm, smax[w]);
    float e0 = expf(l0 - bm), e1 = expf(l1 - bm);
    float den = e0 + e1;
    float num = e0 * v0 + e1 * v1;
    #pragma unroll
    for (int o = 16; o; o >>= 1) {
        den += __shfl_xor_sync(0xffffffffu, den, o);
        num += __shfl_xor_sync(0xffffffffu, num, o);
    }
    __shared__ float sden[8], snum[8];
    if (lane == 0) { sden[wid] = den; snum[wid] = num; }
    __syncthreads();
    if (t == 0) {
        float dS = 0.f, nS = 0.f;
        #pragma unroll
        for (int w = 0; w < 8; ++w) { dS += sden[w]; nS += snum[w]; }
        out[row] = nS / dS;
    }
}

// ---------------- launch ------------------------------------------------------
extern "C" void kernel_launch(void* const* d_in, const int* in_sizes, int n_in,
                              void* d_out, int out_size)
{
    (void)in_sizes; (void)n_in; (void)out_size;
    const float* F   = (const float*)d_in[0];
    const float* D   = (const float*)d_in[1];
    const float* Wq  = (const float*)d_in[2];
    const float* Wk  = (const float*)d_in[3];
    const float* Wv  = (const float*)d_in[4];
    const float* gf  = (const float*)d_in[5];
    const float* bf  = (const float*)d_in[6];
    const float* gp  = (const float*)d_in[7];
    const float* bp  = (const float*)d_in[8];
    const float* Wpt = (const float*)d_in[9];
    const float* bpt = (const float*)d_in[10];
    const float* Wph = (const float*)d_in[11];
    float* out = (float*)d_out;

    prep_kernel<<<1, 256>>>(Wv, gp, bp, Wpt, bpt, Wph);
    ln_kernel<<<256, 256>>>(F, gf, bf);
    gemm_qk<<<dim3(4, 32, 2), 256>>>(Wq, Wk);
    bias_kernel<<<65536, 256>>>(D);
    gemm_att<<<dim3(8, 8, 4), 256>>>();
    softmax_kernel<<<2048, 256>>>(out);
}

// round 2
// speedup vs baseline: 1.4297x; 1.4297x over previous
#include <cuda_runtime.h>

#define LNEPS 1e-3f
#define SCALAR 0.0625f   // 1/sqrt(256)

// ---------------- scratch (device globals; no allocations allowed) ----------
__device__ float g_Fn[2048 * 256];        // LayerNorm(F)
__device__ float g_Q[2048 * 256];         // pre-scaled by SCALAR
__device__ float g_K[2048 * 256];
__device__ float g_L[4 * 512 * 512];      // (SCALAR*Q) @ K^T
__device__ float g_bias[4 * 512 * 512];   // scaled pair bias
__device__ float g_vsum[2048];            // row sums of V
__device__ float g_sd[64];                // scalar * g_p[d] * w_eff[d]
__device__ float g_sc[2];                 // [0]=sum(g_sd), [1]=scalar*const term
__device__ float g_wvsum[256];            // Wv @ ones

// ---------------- prep A: fold pair-path weights (tiny) ----------------------
__global__ __launch_bounds__(64) void prep_small(
    const float* __restrict__ gp, const float* __restrict__ bp,
    const float* __restrict__ Wpt, const float* __restrict__ bpt,
    const float* __restrict__ Wph)
{
    __shared__ float weff[64];
    int t = threadIdx.x;
    float acc = 0.f;
    #pragma unroll 8
    for (int p = 0; p < 128; ++p) acc += Wpt[t * 128 + p] * Wph[p];
    weff[t] = acc;
    g_sd[t] = SCALAR * gp[t] * acc;
    __syncthreads();
    if (t == 0) {
        float S = 0.f, C = 0.f;
        for (int d = 0; d < 64; ++d) { S += SCALAR * gp[d] * weff[d]; C += bp[d] * weff[d]; }
        float C2 = 0.f;
        for (int p = 0; p < 128; ++p) C2 += bpt[p] * Wph[p];
        g_sc[0] = S;
        g_sc[1] = SCALAR * (C + C2);
    }
}

// ---------------- prep B: wvsum[f] = sum_a Wv[f,a]  (one warp per f) ---------
__global__ __launch_bounds__(256) void prep_wvsum(const float* __restrict__ Wv)
{
    int warp = threadIdx.x >> 5, lane = threadIdx.x & 31;
    int f = blockIdx.x * 8 + warp;
    const float* row = Wv + (size_t)f * 256;
    float acc = 0.f;
    #pragma unroll
    for (int i = 0; i < 8; ++i) acc += row[lane + 32 * i];
    #pragma unroll
    for (int o = 16; o; o >>= 1) acc += __shfl_xor_sync(0xffffffffu, acc, o);
    if (lane == 0) g_wvsum[f] = acc;
}

// ---------------- LayerNorm(F) + vsum ----------------------------------------
__global__ __launch_bounds__(256) void ln_kernel(
    const float* __restrict__ F, const float* __restrict__ gf,
    const float* __restrict__ bf)
{
    int row  = blockIdx.x * 8 + (threadIdx.x >> 5);
    int lane = threadIdx.x & 31;
    const float* x = F + (size_t)row * 256;
    float4 a = *(const float4*)(x + lane * 4);
    float4 b = *(const float4*)(x + 128 + lane * 4);
    float s = a.x + a.y + a.z + a.w + b.x + b.y + b.z + b.w;
    float q = a.x*a.x + a.y*a.y + a.z*a.z + a.w*a.w
            + b.x*b.x + b.y*b.y + b.z*b.z + b.w*b.w;
    #pragma unroll
    for (int o = 16; o; o >>= 1) {
        s += __shfl_xor_sync(0xffffffffu, s, o);
        q += __shfl_xor_sync(0xffffffffu, q, o);
    }
    float mu   = s * (1.f / 256.f);
    float rinv = rsqrtf(q * (1.f / 256.f) - mu * mu + LNEPS);

    float4 g0 = *(const float4*)(gf + lane * 4);
    float4 b0 = *(const float4*)(bf + lane * 4);
    float4 g1 = *(const float4*)(gf + 128 + lane * 4);
    float4 b1 = *(const float4*)(bf + 128 + lane * 4);
    float4 f0, f1;
    f0.x = (a.x - mu) * rinv * g0.x + b0.x;
    f0.y = (a.y - mu) * rinv * g0.y + b0.y;
    f0.z = (a.z - mu) * rinv * g0.z + b0.z;
    f0.w = (a.w - mu) * rinv * g0.w + b0.w;
    f1.x = (b.x - mu) * rinv * g1.x + b1.x;
    f1.y = (b.y - mu) * rinv * g1.y + b1.y;
    f1.z = (b.z - mu) * rinv * g1.z + b1.z;
    f1.w = (b.w - mu) * rinv * g1.w + b1.w;

    *(float4*)(g_Fn + (size_t)row * 256 + lane * 4)       = f0;
    *(float4*)(g_Fn + (size_t)row * 256 + 128 + lane * 4) = f1;

    float4 w0 = *(const float4*)(g_wvsum + lane * 4);
    float4 w1 = *(const float4*)(g_wvsum + 128 + lane * 4);
    float p = f0.x*w0.x + f0.y*w0.y + f0.z*w0.z + f0.w*w0.w
            + f1.x*w1.x + f1.y*w1.y + f1.z*w1.z + f1.w*w1.w;
    #pragma unroll
    for (int o = 16; o; o >>= 1) p += __shfl_xor_sync(0xffffffffu, p, o);
    if (lane == 0) g_vsum[row] = p;
}

// ---------------- Q = SCALAR*Fn@Wq, K = Fn@Wk  (NN GEMM, 64x64 tile) ---------
__global__ __launch_bounds__(256) void gemm_qk(
    const float* __restrict__ Wq, const float* __restrict__ Wk)
{
    const float* W = blockIdx.z ? Wk : Wq;
    float* C = blockIdx.z ? g_K : g_Q;
    float outscale = blockIdx.z ? 1.0f : SCALAR;
    __shared__ float As[16][68];
    __shared__ float Ws[16][68];
    int t  = threadIdx.x;
    int tx = t & 15, ty = t >> 4;
    int m0 = blockIdx.y * 64, n0 = blockIdx.x * 64;
    float acc[4][4] = {};
    for (int k0 = 0; k0 < 256; k0 += 16) {
        float4 av = *(const float4*)(g_Fn + (size_t)(m0 + (t >> 2)) * 256 + k0 + (t & 3) * 4);
        int km = (t & 3) * 4, mm = t >> 2;
        As[km + 0][mm] = av.x; As[km + 1][mm] = av.y;
        As[km + 2][mm] = av.z; As[km + 3][mm] = av.w;
        float4 wv = *(const float4*)(W + (size_t)(k0 + (t >> 4)) * 256 + n0 + (t & 15) * 4);
        *(float4*)&Ws[t >> 4][(t & 15) * 4] = wv;
        __syncthreads();
        #pragma unroll
        for (int k = 0; k < 16; ++k) {
            float4 a = *(float4*)&As[k][ty * 4];
            float4 w = *(float4*)&Ws[k][tx * 4];
            acc[0][0] += a.x * w.x; acc[0][1] += a.x * w.y; acc[0][2] += a.x * w.z; acc[0][3] += a.x * w.w;
            acc[1][0] += a.y * w.x; acc[1][1] += a.y * w.y; acc[1][2] += a.y * w.z; acc[1][3] += a.y * w.w;
            acc[2][0] += a.z * w.x; acc[2][1] += a.z * w.y; acc[2][2] += a.z * w.z; acc[2][3] += a.z * w.w;
            acc[3][0] += a.w * w.x; acc[3][1] += a.w * w.y; acc[3][2] += a.w * w.z; acc[3][3] += a.w * w.w;
        }
        __syncthreads();
    }
    #pragma unroll
    for (int i = 0; i < 4; ++i) {
        float4 o;
        o.x = outscale * acc[i][0]; o.y = outscale * acc[i][1];
        o.z = outscale * acc[i][2]; o.w = outscale * acc[i][3];
        *(float4*)(C + (size_t)(m0 + ty * 4 + i) * 256 + n0 + tx * 4) = o;
    }
}

// ---------------- pair bias from D (HBM-bound, MLP=4) ------------------------
// 8 lanes per 64-float row; each thread handles 2 rows (4 independent LDG.128).
__global__ __launch_bounds__(256) void bias_kernel(const float* __restrict__ D)
{
    int t = threadIdx.x;
    int lane = t & 31, warp = t >> 5;
    int sub = lane >> 3;     // 0..3
    int c   = lane & 7;      // 0..7
    size_t row0 = (size_t)blockIdx.x * 64 + warp * 8 + sub;
    size_t row1 = row0 + 4;
    const float* p0 = D + row0 * 64;
    const float* p1 = D + row1 * 64;
    float4 a0 = *(const float4*)(p0 + c * 4);
    float4 b0 = *(const float4*)(p0 + 32 + c * 4);
    float4 a1 = *(const float4*)(p1 + c * 4);
    float4 b1 = *(const float4*)(p1 + 32 + c * 4);
    float4 s0 = *(const float4*)(g_sd + c * 4);
    float4 s1 = *(const float4*)(g_sd + 32 + c * 4);

    float sum0 = a0.x + a0.y + a0.z + a0.w + b0.x + b0.y + b0.z + b0.w;
    float sq0  = a0.x*a0.x + a0.y*a0.y + a0.z*a0.z + a0.w*a0.w
               + b0.x*b0.x + b0.y*b0.y + b0.z*b0.z + b0.w*b0.w;
    float dp0  = a0.x*s0.x + a0.y*s0.y + a0.z*s0.z + a0.w*s0.w
               + b0.x*s1.x + b0.y*s1.y + b0.z*s1.z + b0.w*s1.w;
    float sum1 = a1.x + a1.y + a1.z + a1.w + b1.x + b1.y + b1.z + b1.w;
    float sq1  = a1.x*a1.x + a1.y*a1.y + a1.z*a1.z + a1.w*a1.w
               + b1.x*b1.x + b1.y*b1.y + b1.z*b1.z + b1.w*b1.w;
    float dp1  = a1.x*s0.x + a1.y*s0.y + a1.z*s0.z + a1.w*s0.w
               + b1.x*s1.x + b1.y*s1.y + b1.z*s1.z + b1.w*s1.w;

    #pragma unroll
    for (int o = 4; o; o >>= 1) {
        sum0 += __shfl_xor_sync(0xffffffffu, sum0, o);
        sq0  += __shfl_xor_sync(0xffffffffu, sq0,  o);
        dp0  += __shfl_xor_sync(0xffffffffu, dp0,  o);
        sum1 += __shfl_xor_sync(0xffffffffu, sum1, o);
        sq1  += __shfl_xor_sync(0xffffffffu, sq1,  o);
        dp1  += __shfl_xor_sync(0xffffffffu, dp1,  o);
    }
    if (c == 0) {
        float S = g_sc[0], C = g_sc[1];
        float mu0   = sum0 * (1.f / 64.f);
        float rinv0 = rsqrtf(sq0 * (1.f / 64.f) - mu0 * mu0 + LNEPS);
        g_bias[row0] = rinv0 * (dp0 - mu0 * S) + C;
        float mu1   = sum1 * (1.f / 64.f);
        float rinv1 = rsqrtf(sq1 * (1.f / 64.f) - mu1 * mu1 + LNEPS);
        g_bias[row1] = rinv1 * (dp1 - mu1 * S) + C;
    }
}

// ---------------- L = (SCALAR*Q) @ K^T per batch (NT GEMM, pure store) -------
__global__ __launch_bounds__(256) void gemm_att()
{
    int b = blockIdx.z;
    const float* Q = g_Q + (size_t)b * 512 * 256;
    const float* K = g_K + (size_t)b * 512 * 256;
    float* C = g_L + (size_t)b * 512 * 512;
    __shared__ float As[16][68];
    __shared__ float Bs[16][68];
    int t  = threadIdx.x;
    int tx = t & 15, ty = t >> 4;
    int m0 = blockIdx.y * 64, n0 = blockIdx.x * 64;
    float acc[4][4] = {};
    for (int k0 = 0; k0 < 256; k0 += 16) {
        int km = (t & 3) * 4, mm = t >> 2;
        float4 av = *(const float4*)(Q + (size_t)(m0 + mm) * 256 + k0 + km);
        As[km + 0][mm] = av.x; As[km + 1][mm] = av.y;
        As[km + 2][mm] = av.z; As[km + 3][mm] = av.w;
        float4 bv = *(const float4*)(K + (size_t)(n0 + mm) * 256 + k0 + km);
        Bs[km + 0][mm] = bv.x; Bs[km + 1][mm] = bv.y;
        Bs[km + 2][mm] = bv.z; Bs[km + 3][mm] = bv.w;
        __syncthreads();
        #pragma unroll
        for (int k = 0; k < 16; ++k) {
            float4 a = *(float4*)&As[k][ty * 4];
            float4 w = *(float4*)&Bs[k][tx * 4];
            acc[0][0] += a.x * w.x; acc[0][1] += a.x * w.y; acc[0][2] += a.x * w.z; acc[0][3] += a.x * w.w;
            acc[1][0] += a.y * w.x; acc[1][1] += a.y * w.y; acc[1][2] += a.y * w.z; acc[1][3] += a.y * w.w;
            acc[2][0] += a.z * w.x; acc[2][1] += a.z * w.y; acc[2][2] += a.z * w.z; acc[2][3] += a.z * w.w;
            acc[3][0] += a.w * w.x; acc[3][1] += a.w * w.y; acc[3][2] += a.w * w.z; acc[3][3] += a.w * w.w;
        }
        __syncthreads();
    }
    #pragma unroll
    for (int i = 0; i < 4; ++i) {
        float4 o;
        o.x = acc[i][0]; o.y = acc[i][1]; o.z = acc[i][2]; o.w = acc[i][3];
        *(float4*)(C + (size_t)(m0 + ty * 4 + i) * 512 + n0 + tx * 4) = o;
    }
}

// ---------------- softmax + weighted vsum reduction --------------------------
__global__ __launch_bounds__(256) void softmax_kernel(float* __restrict__ out)
{
    int row = blockIdx.x;                     // row = b*512 + q
    const float* l  = g_L + (size_t)row * 512;
    const float* bi = g_bias + (size_t)row * 512;
    const float* vb = g_vsum + ((row >> 9) << 9);
    int t = threadIdx.x;
    int lane = t & 31, wid = t >> 5;
    float l0 = l[t] + bi[t];
    float l1 = l[t + 256] + bi[t + 256];
    float v0 = vb[t], v1 = vb[t + 256];
    float m = fmaxf(l0, l1);
    #pragma unroll
    for (int o = 16; o; o >>= 1) m = fmaxf(m, __shfl_xor_sync(0xffffffffu, m, o));
    __shared__ float smax[8];
    if (lane == 0) smax[wid] = m;
    __syncthreads();
    float bm = smax[0];
    #pragma unroll
    for (int w = 1; w < 8; ++w) bm = fmaxf(bm, smax[w]);
    float e0 = expf(l0 - bm), e1 = expf(l1 - bm);
    float den = e0 + e1;
    float num = e0 * v0 + e1 * v1;
    #pragma unroll
    for (int o = 16; o; o >>= 1) {
        den += __shfl_xor_sync(0xffffffffu, den, o);
        num += __shfl_xor_sync(0xffffffffu, num, o);
    }
    __shared__ float sden[8], snum[8];
    if (lane == 0) { sden[wid] = den; snum[wid] = num; }
    __syncthreads();
    if (t == 0) {
        float dS = 0.f, nS = 0.f;
        #pragma unroll
        for (int w = 0; w < 8; ++w) { dS += sden[w]; nS += snum[w]; }
        out[row] = nS / dS;
    }
}

// ---------------- launch ------------------------------------------------------
extern "C" void kernel_launch(void* const* d_in, const int* in_sizes, int n_in,
                              void* d_out, int out_size)
{
    (void)in_sizes; (void)n_in; (void)out_size;
    const float* F   = (const float*)d_in[0];
    const float* D   = (const float*)d_in[1];
    const float* Wq  = (const float*)d_in[2];
    const float* Wk  = (const float*)d_in[3];
    const float* Wv  = (const float*)d_in[4];
    const float* gf  = (const float*)d_in[5];
    const float* bf  = (const float*)d_in[6];
    const float* gp  = (const float*)d_in[7];
    const float* bp  = (const float*)d_in[8];
    const float* Wpt = (const float*)d_in[9];
    const float* bpt = (const float*)d_in[10];
    const float* Wph = (const float*)d_in[11];
    float* out = (float*)d_out;

    cudaStream_t s2;
    cudaStreamCreateWithFlags(&s2, cudaStreamNonBlocking);
    cudaEvent_t ev1, ev2;
    cudaEventCreateWithFlags(&ev1, cudaEventDisableTiming);
    cudaEventCreateWithFlags(&ev2, cudaEventDisableTiming);

    // stream 0: prep_small, then fork bias onto s2
    prep_small<<<1, 64>>>(gp, bp, Wpt, bpt, Wph);
    cudaEventRecord(ev1, 0);
    cudaStreamWaitEvent(s2, ev1, 0);
    bias_kernel<<<16384, 256, 0, s2>>>(D);           // DRAM-bound leg

    // stream 0: compute leg
    prep_wvsum<<<32, 256>>>(Wv);
    ln_kernel<<<256, 256>>>(F, gf, bf);
    gemm_qk<<<dim3(4, 32, 2), 256>>>(Wq, Wk);
    gemm_att<<<dim3(8, 8, 4), 256>>>();

    // join and finish
    cudaEventRecord(ev2, s2);
    cudaStreamWaitEvent(0, ev2, 0);
    softmax_kernel<<<2048, 256>>>(out);

    cudaEventDestroy(ev1);
    cudaEventDestroy(ev2);
    cudaStreamDestroy(s2);
}

// round 4
// speedup vs baseline: 1.5457x; 1.0811x over previous
#include <cuda_runtime.h>

#define LNEPS 1e-3f
#define SCALAR 0.0625f   // 1/sqrt(256)

// ---------------- scratch (device globals; no allocations allowed) ----------
__device__ float g_Fn[2048 * 256];        // LayerNorm(F)
__device__ float g_Q[2048 * 256];         // pre-scaled by SCALAR
__device__ float g_K[2048 * 256];
__device__ float g_L[4 * 512 * 512];      // (SCALAR*Q) @ K^T
__device__ float g_bias[4 * 512 * 512];   // scaled pair bias
__device__ float g_vsum[2048];            // row sums of V
__device__ float g_sd[64];                // scalar * g_p[d] * w_eff[d]
__device__ float g_sc[2];                 // [0]=sum(g_sd), [1]=scalar*const term
__device__ float g_wvsum[256];            // Wv @ ones

// ---------------- prep A: fold pair-path weights (tiny) ----------------------
__global__ __launch_bounds__(64) void prep_small(
    const float* __restrict__ gp, const float* __restrict__ bp,
    const float* __restrict__ Wpt, const float* __restrict__ bpt,
    const float* __restrict__ Wph)
{
    __shared__ float weff[64];
    int t = threadIdx.x;
    float acc = 0.f;
    #pragma unroll 8
    for (int p = 0; p < 128; ++p) acc += Wpt[t * 128 + p] * Wph[p];
    weff[t] = acc;
    g_sd[t] = SCALAR * gp[t] * acc;
    __syncthreads();
    if (t == 0) {
        float S = 0.f, C = 0.f;
        for (int d = 0; d < 64; ++d) { S += SCALAR * gp[d] * weff[d]; C += bp[d] * weff[d]; }
        float C2 = 0.f;
        for (int p = 0; p < 128; ++p) C2 += bpt[p] * Wph[p];
        g_sc[0] = S;
        g_sc[1] = SCALAR * (C + C2);
    }
}

// ---------------- prep B: wvsum[f] = sum_a Wv[f,a]  (one warp per f) ---------
__global__ __launch_bounds__(256) void prep_wvsum(const float* __restrict__ Wv)
{
    int warp = threadIdx.x >> 5, lane = threadIdx.x & 31;
    int f = blockIdx.x * 8 + warp;
    const float* row = Wv + (size_t)f * 256;
    float acc = 0.f;
    #pragma unroll
    for (int i = 0; i < 8; ++i) acc += row[lane + 32 * i];
    #pragma unroll
    for (int o = 16; o; o >>= 1) acc += __shfl_xor_sync(0xffffffffu, acc, o);
    if (lane == 0) g_wvsum[f] = acc;
}

// ---------------- LayerNorm(F) + vsum ----------------------------------------
__global__ __launch_bounds__(256) void ln_kernel(
    const float* __restrict__ F, const float* __restrict__ gf,
    const float* __restrict__ bf)
{
    int row  = blockIdx.x * 8 + (threadIdx.x >> 5);
    int lane = threadIdx.x & 31;
    const float* x = F + (size_t)row * 256;
    float4 a = *(const float4*)(x + lane * 4);
    float4 b = *(const float4*)(x + 128 + lane * 4);
    float s = a.x + a.y + a.z + a.w + b.x + b.y + b.z + b.w;
    float q = a.x*a.x + a.y*a.y + a.z*a.z + a.w*a.w
            + b.x*b.x + b.y*b.y + b.z*b.z + b.w*b.w;
    #pragma unroll
    for (int o = 16; o; o >>= 1) {
        s += __shfl_xor_sync(0xffffffffu, s, o);
        q += __shfl_xor_sync(0xffffffffu, q, o);
    }
    float mu   = s * (1.f / 256.f);
    float rinv = rsqrtf(q * (1.f / 256.f) - mu * mu + LNEPS);

    float4 g0 = *(const float4*)(gf + lane * 4);
    float4 b0 = *(const float4*)(bf + lane * 4);
    float4 g1 = *(const float4*)(gf + 128 + lane * 4);
    float4 b1 = *(const float4*)(bf + 128 + lane * 4);
    float4 f0, f1;
    f0.x = (a.x - mu) * rinv * g0.x + b0.x;
    f0.y = (a.y - mu) * rinv * g0.y + b0.y;
    f0.z = (a.z - mu) * rinv * g0.z + b0.z;
    f0.w = (a.w - mu) * rinv * g0.w + b0.w;
    f1.x = (b.x - mu) * rinv * g1.x + b1.x;
    f1.y = (b.y - mu) * rinv * g1.y + b1.y;
    f1.z = (b.z - mu) * rinv * g1.z + b1.z;
    f1.w = (b.w - mu) * rinv * g1.w + b1.w;

    *(float4*)(g_Fn + (size_t)row * 256 + lane * 4)       = f0;
    *(float4*)(g_Fn + (size_t)row * 256 + 128 + lane * 4) = f1;

    float4 w0 = *(const float4*)(g_wvsum + lane * 4);
    float4 w1 = *(const float4*)(g_wvsum + 128 + lane * 4);
    float p = f0.x*w0.x + f0.y*w0.y + f0.z*w0.z + f0.w*w0.w
            + f1.x*w1.x + f1.y*w1.y + f1.z*w1.z + f1.w*w1.w;
    #pragma unroll
    for (int o = 16; o; o >>= 1) p += __shfl_xor_sync(0xffffffffu, p, o);
    if (lane == 0) g_vsum[row] = p;
}

// ---------------- GEMM 1: Q = SCALAR*Fn@Wq, K = Fn@Wk ------------------------
// 128x64 tile, 256 threads, 8x4 per-thread tile, k-step 16, double-buffered.
__global__ __launch_bounds__(256) void gemm_qk(
    const float* __restrict__ Wq, const float* __restrict__ Wk)
{
    const float* W = blockIdx.z ? Wk : Wq;
    float* C = blockIdx.z ? g_K : g_Q;
    const float outscale = blockIdx.z ? 1.0f : SCALAR;
    __shared__ float As[2][16][132];   // [buf][k][m]
    __shared__ float Bs[2][16][68];    // [buf][k][n]
    int t  = threadIdx.x;
    int tx = t & 15, ty = t >> 4;
    int m0 = blockIdx.y * 128, n0 = blockIdx.x * 64;

    int arow = t >> 2;           // 0..63 (rows arow, arow+64)
    int ak4  = (t & 3) * 4;      // k offset within 16
    int bk   = t >> 4;           // 0..15
    int bn4  = (t & 15) * 4;

    const float* Aptr0 = g_Fn + (size_t)(m0 + arow) * 256 + ak4;
    const float* Aptr1 = Aptr0 + 64 * 256;
    const float* Bptr  = W + (size_t)bk * 256 + n0 + bn4;

    float acc[8][4] = {};
    // preload k-tile 0
    {
        float4 a0 = *(const float4*)(Aptr0);
        float4 a1 = *(const float4*)(Aptr1);
        float4 bv = *(const float4*)(Bptr);
        As[0][ak4+0][arow] = a0.x; As[0][ak4+1][arow] = a0.y;
        As[0][ak4+2][arow] = a0.z; As[0][ak4+3][arow] = a0.w;
        As[0][ak4+0][arow+64] = a1.x; As[0][ak4+1][arow+64] = a1.y;
        As[0][ak4+2][arow+64] = a1.z; As[0][ak4+3][arow+64] = a1.w;
        *(float4*)&Bs[0][bk][bn4] = bv;
    }
    __syncthreads();
    int cur = 0;
    for (int kt = 0; kt < 16; ++kt) {
        float4 na0, na1, nb;
        if (kt < 15) {
            na0 = *(const float4*)(Aptr0 + (kt + 1) * 16);
            na1 = *(const float4*)(Aptr1 + (kt + 1) * 16);
            nb  = *(const float4*)(Bptr + (size_t)(kt + 1) * 16 * 256);
        }
        #pragma unroll
        for (int k = 0; k < 16; ++k) {
            float4 a0 = *(float4*)&As[cur][k][ty * 8];
            float4 a1 = *(float4*)&As[cur][k][ty * 8 + 4];
            float4 b  = *(float4*)&Bs[cur][k][tx * 4];
            acc[0][0] += a0.x * b.x; acc[0][1] += a0.x * b.y; acc[0][2] += a0.x * b.z; acc[0][3] += a0.x * b.w;
            acc[1][0] += a0.y * b.x; acc[1][1] += a0.y * b.y; acc[1][2] += a0.y * b.z; acc[1][3] += a0.y * b.w;
            acc[2][0] += a0.z * b.x; acc[2][1] += a0.z * b.y; acc[2][2] += a0.z * b.z; acc[2][3] += a0.z * b.w;
            acc[3][0] += a0.w * b.x; acc[3][1] += a0.w * b.y; acc[3][2] += a0.w * b.z; acc[3][3] += a0.w * b.w;
            acc[4][0] += a1.x * b.x; acc[4][1] += a1.x * b.y; acc[4][2] += a1.x * b.z; acc[4][3] += a1.x * b.w;
            acc[5][0] += a1.y * b.x; acc[5][1] += a1.y * b.y; acc[5][2] += a1.y * b.z; acc[5][3] += a1.y * b.w;
            acc[6][0] += a1.z * b.x; acc[6][1] += a1.z * b.y; acc[6][2] += a1.z * b.z; acc[6][3] += a1.z * b.w;
            acc[7][0] += a1.w * b.x; acc[7][1] += a1.w * b.y; acc[7][2] += a1.w * b.z; acc[7][3] += a1.w * b.w;
        }
        if (kt < 15) {
            int nxt = cur ^ 1;
            As[nxt][ak4+0][arow] = na0.x; As[nxt][ak4+1][arow] = na0.y;
            As[nxt][ak4+2][arow] = na0.z; As[nxt][ak4+3][arow] = na0.w;
            As[nxt][ak4+0][arow+64] = na1.x; As[nxt][ak4+1][arow+64] = na1.y;
            As[nxt][ak4+2][arow+64] = na1.z; As[nxt][ak4+3][arow+64] = na1.w;
            *(float4*)&Bs[nxt][bk][bn4] = nb;
        }
        __syncthreads();
        cur ^= 1;
    }
    #pragma unroll
    for (int i = 0; i < 8; ++i) {
        float4 o;
        o.x = outscale * acc[i][0]; o.y = outscale * acc[i][1];
        o.z = outscale * acc[i][2]; o.w = outscale * acc[i][3];
        *(float4*)(C + (size_t)(m0 + ty * 8 + i) * 256 + n0 + tx * 4) = o;
    }
}

// ---------------- GEMM 2: L = (SCALAR*Q) @ K^T per batch ---------------------
// 128x64 tile, 8x4 per-thread, k-step 16, double-buffered.
__global__ __launch_bounds__(256) void gemm_att()
{
    int b = blockIdx.z;
    const float* Q = g_Q + (size_t)b * 512 * 256;
    const float* K = g_K + (size_t)b * 512 * 256;
    float* C = g_L + (size_t)b * 512 * 512;
    __shared__ float As[2][16][132];
    __shared__ float Bs[2][16][68];
    int t  = threadIdx.x;
    int tx = t & 15, ty = t >> 4;
    int m0 = blockIdx.y * 128, n0 = blockIdx.x * 64;

    int arow = t >> 2;
    int ak4  = (t & 3) * 4;

    const float* Aptr0 = Q + (size_t)(m0 + arow) * 256 + ak4;
    const float* Aptr1 = Aptr0 + 64 * 256;
    const float* Bptr  = K + (size_t)(n0 + arow) * 256 + ak4;  // 64 rows of K

    float acc[8][4] = {};
    {
        float4 a0 = *(const float4*)(Aptr0);
        float4 a1 = *(const float4*)(Aptr1);
        float4 bv = *(const float4*)(Bptr);
        As[0][ak4+0][arow] = a0.x; As[0][ak4+1][arow] = a0.y;
        As[0][ak4+2][arow] = a0.z; As[0][ak4+3][arow] = a0.w;
        As[0][ak4+0][arow+64] = a1.x; As[0][ak4+1][arow+64] = a1.y;
        As[0][ak4+2][arow+64] = a1.z; As[0][ak4+3][arow+64] = a1.w;
        Bs[0][ak4+0][arow] = bv.x; Bs[0][ak4+1][arow] = bv.y;
        Bs[0][ak4+2][arow] = bv.z; Bs[0][ak4+3][arow] = bv.w;
    }
    __syncthreads();
    int cur = 0;
    for (int kt = 0; kt < 16; ++kt) {
        float4 na0, na1, nb;
        if (kt < 15) {
            na0 = *(const float4*)(Aptr0 + (kt + 1) * 16);
            na1 = *(const float4*)(Aptr1 + (kt + 1) * 16);
            nb  = *(const float4*)(Bptr + (kt + 1) * 16);
        }
        #pragma unroll
        for (int k = 0; k < 16; ++k) {
            float4 a0 = *(float4*)&As[cur][k][ty * 8];
            float4 a1 = *(float4*)&As[cur][k][ty * 8 + 4];
            float4 bv = *(float4*)&Bs[cur][k][tx * 4];
            acc[0][0] += a0.x * bv.x; acc[0][1] += a0.x * bv.y; acc[0][2] += a0.x * bv.z; acc[0][3] += a0.x * bv.w;
            acc[1][0] += a0.y * bv.x; acc[1][1] += a0.y * bv.y; acc[1][2] += a0.y * bv.z; acc[1][3] += a0.y * bv.w;
            acc[2][0] += a0.z * bv.x; acc[2][1] += a0.z * bv.y; acc[2][2] += a0.z * bv.z; acc[2][3] += a0.z * bv.w;
            acc[3][0] += a0.w * bv.x; acc[3][1] += a0.w * bv.y; acc[3][2] += a0.w * bv.z; acc[3][3] += a0.w * bv.w;
            acc[4][0] += a1.x * bv.x; acc[4][1] += a1.x * bv.y; acc[4][2] += a1.x * bv.z; acc[4][3] += a1.x * bv.w;
            acc[5][0] += a1.y * bv.x; acc[5][1] += a1.y * bv.y; acc[5][2] += a1.y * bv.z; acc[5][3] += a1.y * bv.w;
            acc[6][0] += a1.z * bv.x; acc[6][1] += a1.z * bv.y; acc[6][2] += a1.z * bv.z; acc[6][3] += a1.z * bv.w;
            acc[7][0] += a1.w * bv.x; acc[7][1] += a1.w * bv.y; acc[7][2] += a1.w * bv.z; acc[7][3] += a1.w * bv.w;
        }
        if (kt < 15) {
            int nxt = cur ^ 1;
            As[nxt][ak4+0][arow] = na0.x; As[nxt][ak4+1][arow] = na0.y;
            As[nxt][ak4+2][arow] = na0.z; As[nxt][ak4+3][arow] = na0.w;
            As[nxt][ak4+0][arow+64] = na1.x; As[nxt][ak4+1][arow+64] = na1.y;
            As[nxt][ak4+2][arow+64] = na1.z; As[nxt][ak4+3][arow+64] = na1.w;
            Bs[nxt][ak4+0][arow] = nb.x; Bs[nxt][ak4+1][arow] = nb.y;
            Bs[nxt][ak4+2][arow] = nb.z; Bs[nxt][ak4+3][arow] = nb.w;
        }
        __syncthreads();
        cur ^= 1;
    }
    #pragma unroll
    for (int i = 0; i < 8; ++i) {
        float4 o;
        o.x = acc[i][0]; o.y = acc[i][1]; o.z = acc[i][2]; o.w = acc[i][3];
        *(float4*)(C + (size_t)(m0 + ty * 8 + i) * 512 + n0 + tx * 4) = o;
    }
}

// ---------------- pair bias from D (HBM-bound, MLP=4) ------------------------
__global__ __launch_bounds__(256) void bias_kernel(const float* __restrict__ D)
{
    int t = threadIdx.x;
    int lane = t & 31, warp = t >> 5;
    int sub = lane >> 3;     // 0..3
    int c   = lane & 7;      // 0..7
    size_t row0 = (size_t)blockIdx.x * 64 + warp * 8 + sub;
    size_t row1 = row0 + 4;
    const float* p0 = D + row0 * 64;
    const float* p1 = D + row1 * 64;
    float4 a0 = *(const float4*)(p0 + c * 4);
    float4 b0 = *(const float4*)(p0 + 32 + c * 4);
    float4 a1 = *(const float4*)(p1 + c * 4);
    float4 b1 = *(const float4*)(p1 + 32 + c * 4);
    float4 s0 = *(const float4*)(g_sd + c * 4);
    float4 s1 = *(const float4*)(g_sd + 32 + c * 4);

    float sum0 = a0.x + a0.y + a0.z + a0.w + b0.x + b0.y + b0.z + b0.w;
    float sq0  = a0.x*a0.x + a0.y*a0.y + a0.z*a0.z + a0.w*a0.w
               + b0.x*b0.x + b0.y*b0.y + b0.z*b0.z + b0.w*b0.w;
    float dp0  = a0.x*s0.x + a0.y*s0.y + a0.z*s0.z + a0.w*s0.w
               + b0.x*s1.x + b0.y*s1.y + b0.z*s1.z + b0.w*s1.w;
    float sum1 = a1.x + a1.y + a1.z + a1.w + b1.x + b1.y + b1.z + b1.w;
    float sq1  = a1.x*a1.x + a1.y*a1.y + a1.z*a1.z + a1.w*a1.w
               + b1.x*b1.x + b1.y*b1.y + b1.z*b1.z + b1.w*b1.w;
    float dp1  = a1.x*s0.x + a1.y*s0.y + a1.z*s0.z + a1.w*s0.w
               + b1.x*s1.x + b1.y*s1.y + b1.z*s1.z + b1.w*s1.w;

    #pragma unroll
    for (int o = 4; o; o >>= 1) {
        sum0 += __shfl_xor_sync(0xffffffffu, sum0, o);
        sq0  += __shfl_xor_sync(0xffffffffu, sq0,  o);
        dp0  += __shfl_xor_sync(0xffffffffu, dp0,  o);
        sum1 += __shfl_xor_sync(0xffffffffu, sum1, o);
        sq1  += __shfl_xor_sync(0xffffffffu, sq1,  o);
        dp1  += __shfl_xor_sync(0xffffffffu, dp1,  o);
    }
    if (c == 0) {
        float S = g_sc[0], C = g_sc[1];
        float mu0   = sum0 * (1.f / 64.f);
        float rinv0 = rsqrtf(sq0 * (1.f / 64.f) - mu0 * mu0 + LNEPS);
        g_bias[row0] = rinv0 * (dp0 - mu0 * S) + C;
        float mu1   = sum1 * (1.f / 64.f);
        float rinv1 = rsqrtf(sq1 * (1.f / 64.f) - mu1 * mu1 + LNEPS);
        g_bias[row1] = rinv1 * (dp1 - mu1 * S) + C;
    }
}

// ---------------- softmax + weighted vsum reduction --------------------------
__global__ __launch_bounds__(256) void softmax_kernel(float* __restrict__ out)
{
    int row = blockIdx.x;                     // row = b*512 + q
    const float* l  = g_L + (size_t)row * 512;
    const float* bi = g_bias + (size_t)row * 512;
    const float* vb = g_vsum + ((row >> 9) << 9);
    int t = threadIdx.x;
    int lane = t & 31, wid = t >> 5;
    float l0 = l[t] + bi[t];
    float l1 = l[t + 256] + bi[t + 256];
    float v0 = vb[t], v1 = vb[t + 256];
    float m = fmaxf(l0, l1);
    #pragma unroll
    for (int o = 16; o; o >>= 1) m = fmaxf(m, __shfl_xor_sync(0xffffffffu, m, o));
    __shared__ float smax[8];
    if (lane == 0) smax[wid] = m;
    __syncthreads();
    float bm = smax[0];
    #pragma unroll
    for (int w = 1; w < 8; ++w) bm = fmaxf(bm, smax[w]);
    float e0 = expf(l0 - bm), e1 = expf(l1 - bm);
    float den = e0 + e1;
    float num = e0 * v0 + e1 * v1;
    #pragma unroll
    for (int o = 16; o; o >>= 1) {
        den += __shfl_xor_sync(0xffffffffu, den, o);
        num += __shfl_xor_sync(0xffffffffu, num, o);
    }
    __shared__ float sden[8], snum[8];
    if (lane == 0) { sden[wid] = den; snum[wid] = num; }
    __syncthreads();
    if (t == 0) {
        float dS = 0.f, nS = 0.f;
        #pragma unroll
        for (int w = 0; w < 8; ++w) { dS += sden[w]; nS += snum[w]; }
        out[row] = nS / dS;
    }
}

// ---------------- launch ------------------------------------------------------
extern "C" void kernel_launch(void* const* d_in, const int* in_sizes, int n_in,
                              void* d_out, int out_size)
{
    (void)in_sizes; (void)n_in; (void)out_size;
    const float* F   = (const float*)d_in[0];
    const float* D   = (const float*)d_in[1];
    const float* Wq  = (const float*)d_in[2];
    const float* Wk  = (const float*)d_in[3];
    const float* Wv  = (const float*)d_in[4];
    const float* gf  = (const float*)d_in[5];
    const float* bf  = (const float*)d_in[6];
    const float* gp  = (const float*)d_in[7];
    const float* bp  = (const float*)d_in[8];
    const float* Wpt = (const float*)d_in[9];
    const float* bpt = (const float*)d_in[10];
    const float* Wph = (const float*)d_in[11];
    float* out = (float*)d_out;

    cudaStream_t s2;
    cudaStreamCreateWithFlags(&s2, cudaStreamNonBlocking);
    cudaEvent_t ev1, ev2;
    cudaEventCreateWithFlags(&ev1, cudaEventDisableTiming);
    cudaEventCreateWithFlags(&ev2, cudaEventDisableTiming);

    // stream 0: prep_small, then fork bias onto s2
    prep_small<<<1, 64>>>(gp, bp, Wpt, bpt, Wph);
    cudaEventRecord(ev1, 0);
    cudaStreamWaitEvent(s2, ev1, 0);
    bias_kernel<<<16384, 256, 0, s2>>>(D);           // DRAM-bound leg

    // stream 0: compute leg
    prep_wvsum<<<32, 256>>>(Wv);
    ln_kernel<<<256, 256>>>(F, gf, bf);
    gemm_qk<<<dim3(4, 16, 2), 256>>>(Wq, Wk);
    gemm_att<<<dim3(8, 4, 4), 256>>>();

    // join and finish
    cudaEventRecord(ev2, s2);
    cudaStreamWaitEvent(0, ev2, 0);
    softmax_kernel<<<2048, 256>>>(out);

    cudaEventDestroy(ev1);
    cudaEventDestroy(ev2);
    cudaStreamDestroy(s2);
}